// round 1
// baseline (speedup 1.0000x reference)
#include <cuda_runtime.h>
#include <math.h>

// Problem sizes (fixed by the reference)
constexpr int BB = 8;
constexpr int NN_ = 2048;
constexpr int DD = 1024;

// Scratch (static device globals — allocation-guard safe)
__device__ float g_qkv[(size_t)BB * NN_ * 3 * DD];     // 192 MB: [16384, 3072] (Q|K|V)
__device__ float g_scores[(size_t)BB * NN_ * NN_];     // 128 MB: [8, 2048, 2048]
__device__ float g_att[(size_t)BB * NN_ * DD];         //  64 MB: [8, 2048, 1024]

// ---------------------------------------------------------------------------
// Tiled SGEMM: C[M,N] = alpha * A[M,K] * op(B) + bias
//   TRANSB=false: B is [K,N] row-major (op(B)=B)
//   TRANSB=true : B is [N,K] row-major (op(B)=B^T)
// Batched via gridDim.z with element strides sA/sB/sC.
// Block tile 128x128, K-tile 8, 256 threads, 8x8 per-thread register tile.
// All M,N divisible by 128 and K divisible by 8 for this problem.
// ---------------------------------------------------------------------------
template <bool TRANSB, bool BIAS>
__global__ __launch_bounds__(256)
void gemm_k(const float* __restrict__ Ag, const float* __restrict__ Bg,
            float* __restrict__ Cg, const float* __restrict__ bias,
            int M, int N, int K, int lda, int ldb, int ldc,
            long long sA, long long sB, long long sC, float alpha)
{
    const int tid = threadIdx.x;
    const int bm = blockIdx.y * 128;
    const int bn = blockIdx.x * 128;

    const float* A = Ag + (long long)blockIdx.z * sA;
    const float* Bp = Bg + (long long)blockIdx.z * sB;
    float* C = Cg + (long long)blockIdx.z * sC;

    __shared__ float As[8][128];
    __shared__ float Bs[8][128];

    // Loader indices
    const int ar = tid >> 1;            // 0..127 (row within tile)
    const int ac = (tid & 1) << 2;      // 0 or 4 (k offset, float4)
    const int br = tid >> 5;            // 0..7   (k row, NN variant)
    const int bc = (tid & 31) << 2;     // 0..124 (n offset, NN variant)

    // Compute mapping: 16x16 thread grid, 8x8 per thread
    const int trow = (tid >> 4) << 3;
    const int tcol = (tid & 15) << 3;

    float acc[8][8];
#pragma unroll
    for (int i = 0; i < 8; ++i)
#pragma unroll
        for (int j = 0; j < 8; ++j) acc[i][j] = 0.0f;

    for (int k0 = 0; k0 < K; k0 += 8) {
        // Load A tile (transposed into As[k][m])
        float4 av = *(const float4*)(A + (long long)(bm + ar) * lda + k0 + ac);
        As[ac + 0][ar] = av.x;
        As[ac + 1][ar] = av.y;
        As[ac + 2][ar] = av.z;
        As[ac + 3][ar] = av.w;

        if (TRANSB) {
            // B is [N,K]: row (bn+ar), cols k0+ac..+3  → Bs[k][n]
            float4 bv = *(const float4*)(Bp + (long long)(bn + ar) * ldb + k0 + ac);
            Bs[ac + 0][ar] = bv.x;
            Bs[ac + 1][ar] = bv.y;
            Bs[ac + 2][ar] = bv.z;
            Bs[ac + 3][ar] = bv.w;
        } else {
            // B is [K,N]: row (k0+br), cols bn+bc..+3  → Bs[k][n]
            float4 bv = *(const float4*)(Bp + (long long)(k0 + br) * ldb + bn + bc);
            *(float4*)&Bs[br][bc] = bv;
        }
        __syncthreads();

#pragma unroll
        for (int k = 0; k < 8; ++k) {
            float ra[8], rb[8];
            *(float4*)&ra[0] = *(const float4*)&As[k][trow];
            *(float4*)&ra[4] = *(const float4*)&As[k][trow + 4];
            *(float4*)&rb[0] = *(const float4*)&Bs[k][tcol];
            *(float4*)&rb[4] = *(const float4*)&Bs[k][tcol + 4];
#pragma unroll
            for (int i = 0; i < 8; ++i)
#pragma unroll
                for (int j = 0; j < 8; ++j)
                    acc[i][j] += ra[i] * rb[j];
        }
        __syncthreads();
    }

    // Epilogue: alpha, bias, vectorized store
#pragma unroll
    for (int i = 0; i < 8; ++i) {
        const long long row = bm + trow + i;
#pragma unroll
        for (int j4 = 0; j4 < 8; j4 += 4) {
            const int col = bn + tcol + j4;
            float4 v;
            v.x = acc[i][j4 + 0] * alpha;
            v.y = acc[i][j4 + 1] * alpha;
            v.z = acc[i][j4 + 2] * alpha;
            v.w = acc[i][j4 + 3] * alpha;
            if (BIAS) {
                v.x += bias[col + 0];
                v.y += bias[col + 1];
                v.z += bias[col + 2];
                v.w += bias[col + 3];
            }
            *(float4*)(C + row * ldc + col) = v;
        }
    }
}

// ---------------------------------------------------------------------------
// Fused dual softmax with mask-fill, one CTA per (b,q) row of 2048.
//   p  = softmax(scores)                       (first softmax)
//   w' = where(mask==0, -1e20, p)
//   w  = softmax(w')   == mask * exp(p - max_masked(p)) / sum(...)
// Degenerate all-masked row -> uniform 1/N (matches reference softmax of
// an all -1e20 row).
// ---------------------------------------------------------------------------
__global__ __launch_bounds__(256)
void dual_softmax_k(float* __restrict__ scores, const int* __restrict__ mask)
{
    const long long row = blockIdx.x;
    float* s = scores + row * 2048;
    const int* mk = mask + row * 2048;
    const int tid = threadIdx.x;

    float v[8];
    int m[8];
#pragma unroll
    for (int i = 0; i < 8; ++i) {
        v[i] = s[tid + (i << 8)];
        m[i] = mk[tid + (i << 8)];
    }

    __shared__ float sred[8];

    // ---- softmax 1: max ----
    float x = -3.0e38f;
#pragma unroll
    for (int i = 0; i < 8; ++i) x = fmaxf(x, v[i]);
#pragma unroll
    for (int o = 16; o > 0; o >>= 1) x = fmaxf(x, __shfl_xor_sync(0xffffffffu, x, o));
    if ((tid & 31) == 0) sred[tid >> 5] = x;
    __syncthreads();
    if (tid == 0) {
        float y = sred[0];
#pragma unroll
        for (int w = 1; w < 8; ++w) y = fmaxf(y, sred[w]);
        sred[0] = y;
    }
    __syncthreads();
    const float m1 = sred[0];
    __syncthreads();

    // ---- softmax 1: exp + sum ----
    float su = 0.0f;
#pragma unroll
    for (int i = 0; i < 8; ++i) {
        v[i] = expf(v[i] - m1);
        su += v[i];
    }
#pragma unroll
    for (int o = 16; o > 0; o >>= 1) su += __shfl_xor_sync(0xffffffffu, su, o);
    if ((tid & 31) == 0) sred[tid >> 5] = su;
    __syncthreads();
    if (tid == 0) {
        float y = 0.0f;
#pragma unroll
        for (int w = 0; w < 8; ++w) y += sred[w];
        sred[0] = y;
    }
    __syncthreads();
    const float inv1 = 1.0f / sred[0];
    __syncthreads();

#pragma unroll
    for (int i = 0; i < 8; ++i) v[i] *= inv1;   // p in [0,1]

    // ---- softmax 2: masked max of p ----
    float x2 = -1.0e30f;
#pragma unroll
    for (int i = 0; i < 8; ++i)
        if (m[i]) x2 = fmaxf(x2, v[i]);
#pragma unroll
    for (int o = 16; o > 0; o >>= 1) x2 = fmaxf(x2, __shfl_xor_sync(0xffffffffu, x2, o));
    if ((tid & 31) == 0) sred[tid >> 5] = x2;
    __syncthreads();
    if (tid == 0) {
        float y = sred[0];
#pragma unroll
        for (int w = 1; w < 8; ++w) y = fmaxf(y, sred[w]);
        sred[0] = y;
    }
    __syncthreads();
    const float m2 = sred[0];
    __syncthreads();

    if (m2 < -1.0e29f) {
        // whole row masked: reference softmax over all -1e20 -> uniform
        const float u = 1.0f / 2048.0f;
#pragma unroll
        for (int i = 0; i < 8; ++i) s[tid + (i << 8)] = u;
        return;
    }

    // ---- softmax 2: masked exp + sum ----
    float su2 = 0.0f;
#pragma unroll
    for (int i = 0; i < 8; ++i) {
        const float e = m[i] ? expf(v[i] - m2) : 0.0f;
        v[i] = e;
        su2 += e;
    }
#pragma unroll
    for (int o = 16; o > 0; o >>= 1) su2 += __shfl_xor_sync(0xffffffffu, su2, o);
    if ((tid & 31) == 0) sred[tid >> 5] = su2;
    __syncthreads();
    if (tid == 0) {
        float y = 0.0f;
#pragma unroll
        for (int w = 0; w < 8; ++w) y += sred[w];
        sred[0] = y;
    }
    __syncthreads();
    const float inv2 = 1.0f / sred[0];

#pragma unroll
    for (int i = 0; i < 8; ++i) s[tid + (i << 8)] = v[i] * inv2;
}

// ---------------------------------------------------------------------------
// Launch
// ---------------------------------------------------------------------------
extern "C" void kernel_launch(void* const* d_in, const int* in_sizes, int n_in,
                              void* d_out, int out_size)
{
    (void)in_sizes; (void)n_in; (void)out_size;

    const float* x     = (const float*)d_in[0];
    const int*   mask  = (const int*)d_in[1];
    const float* W_qkv = (const float*)d_in[2];
    const float* b_qkv = (const float*)d_in[3];
    const float* W_out = (const float*)d_in[4];
    const float* b_out = (const float*)d_in[5];
    float* out = (float*)d_out;

    float *qkv, *scores, *att;
    cudaGetSymbolAddress((void**)&qkv, g_qkv);
    cudaGetSymbolAddress((void**)&scores, g_scores);
    cudaGetSymbolAddress((void**)&att, g_att);

    const dim3 blk(256);
    const int BN_ROWS = BB * NN_;                 // 16384
    const long long sQKV = (long long)NN_ * 3 * DD;  // per-batch stride in qkv
    const long long sSC  = (long long)NN_ * NN_;
    const long long sAT  = (long long)NN_ * DD;

    // 1) qkv = x @ W_qkv + b_qkv        [16384,3072]
    gemm_k<false, true><<<dim3(3 * DD / 128, BN_ROWS / 128, 1), blk>>>(
        x, W_qkv, qkv, b_qkv,
        BN_ROWS, 3 * DD, DD, DD, 3 * DD, 3 * DD,
        0, 0, 0, 1.0f);

    // 2) scores = (Q @ K^T) / sqrt(D)   batched [8](2048x2048)
    gemm_k<true, false><<<dim3(NN_ / 128, NN_ / 128, BB), blk>>>(
        qkv /*Q*/, qkv + DD /*K*/, scores, nullptr,
        NN_, NN_, DD, 3 * DD, 3 * DD, NN_,
        sQKV, sQKV, sSC, 0.03125f /* 1/sqrt(1024) */);

    // 3) dual softmax + mask fill (in place on scores)
    dual_softmax_k<<<BN_ROWS, 256>>>(scores, mask);

    // 4) att = w @ V                    batched [8](2048x1024)
    gemm_k<false, false><<<dim3(DD / 128, NN_ / 128, BB), blk>>>(
        scores, qkv + 2 * DD /*V*/, att, nullptr,
        NN_, DD, NN_, NN_, 3 * DD, DD,
        sSC, sQKV, sAT, 1.0f);

    // 5) out = att @ W_out + b_out      [16384,1024]
    gemm_k<false, true><<<dim3(DD / 128, BN_ROWS / 128, 1), blk>>>(
        att, W_out, out, b_out,
        BN_ROWS, DD, DD, DD, DD, DD,
        0, 0, 0, 1.0f);
}

// round 5
// speedup vs baseline: 3.8652x; 3.8652x over previous
#include <cuda_runtime.h>
#include <cstdint>
#include <math.h>

// ---------------------------------------------------------------------------
// Problem sizes
// ---------------------------------------------------------------------------
constexpr int BBATCH = 8;
constexpr int SEQ    = 2048;
constexpr int DIM    = 1024;

// ---------------------------------------------------------------------------
// Scratch (static device globals — allocation-guard safe)
// ---------------------------------------------------------------------------
__device__ float g_xr    [(size_t)BBATCH * SEQ * DIM];      //  64 MB rounded x
__device__ float g_qkv   [(size_t)BBATCH * SEQ * 3 * DIM];  // 192 MB
__device__ float g_scores[(size_t)BBATCH * SEQ * SEQ];      // 128 MB
__device__ float g_att   [(size_t)BBATCH * SEQ * DIM];      //  64 MB
__device__ float g_vT    [(size_t)BBATCH * DIM * SEQ];      //  64 MB V^T per batch
__device__ float g_wqkvT [(size_t)3 * DIM * DIM];           //  12 MB
__device__ float g_woutT [(size_t)DIM * DIM];               //   4 MB

// ---------------------------------------------------------------------------
// Helpers (all baseline PTX — nothing sm_103a-gated)
// ---------------------------------------------------------------------------
__device__ __forceinline__ float tf32r(float x) {           // round-to-nearest tf32
    uint32_t u;
    asm("cvt.rna.tf32.f32 %0, %1;" : "=r"(u) : "f"(x));
    return __uint_as_float(u);
}

__device__ __forceinline__ uint32_t s2u(const void* p) {
    uint32_t a;
    asm("{ .reg .u64 t; cvta.to.shared.u64 t, %1; cvt.u32.u64 %0, t; }"
        : "=r"(a) : "l"(p));
    return a;
}

__device__ __forceinline__ void cpa16(uint32_t s, const void* g) {
    asm volatile("cp.async.cg.shared.global [%0], [%1], 16;" :: "r"(s), "l"(g));
}

__device__ __forceinline__ void ldsm4(uint32_t r[4], uint32_t addr) {
    asm volatile("ldmatrix.sync.aligned.m8n8.x4.shared.b16 {%0,%1,%2,%3}, [%4];"
                 : "=r"(r[0]), "=r"(r[1]), "=r"(r[2]), "=r"(r[3]) : "r"(addr));
}

__device__ __forceinline__ void mma8(float c[4], const uint32_t a[4],
                                     uint32_t b0, uint32_t b1) {
    asm volatile(
        "mma.sync.aligned.m16n8k8.row.col.f32.tf32.tf32.f32 "
        "{%0,%1,%2,%3}, {%4,%5,%6,%7}, {%8,%9}, {%0,%1,%2,%3};"
        : "+f"(c[0]), "+f"(c[1]), "+f"(c[2]), "+f"(c[3])
        : "r"(a[0]), "r"(a[1]), "r"(a[2]), "r"(a[3]), "r"(b0), "r"(b1));
}

// ---------------------------------------------------------------------------
// tf32 mma.sync GEMM:  C[M,N] = alpha * A[M,K] @ B[N,K]^T  (+bias) (+tf32 round)
// CTA tile 128x128, K-chunk 32, 3-stage cp.async pipeline, 256 threads.
// Both A and B are K-major row-major ([rows, ld]); batched via blockIdx.z.
// ---------------------------------------------------------------------------
constexpr int BM = 128, BN = 128, BK = 32, STAGES = 3;
constexpr int ATILE   = BM * BK * 4;            // 16 KB
constexpr int STAGE_B = 2 * ATILE;              // 32 KB (A + B)
constexpr int GEMM_SMEM = STAGES * STAGE_B + 1024;

template <bool BIAS, bool ROUND>
__global__ __launch_bounds__(256, 2)
void gemm_tc(const float* __restrict__ Ag, const float* __restrict__ Bg,
             float* __restrict__ Cg, const float* __restrict__ bias,
             int lda, int ldb, int ldc,
             long long sA, long long sB, long long sC,
             int K, float alpha)
{
    extern __shared__ char smem_raw[];
    const uint32_t sb = (s2u(smem_raw) + 1023u) & ~1023u;

    const int tid = threadIdx.x, lane = tid & 31, wid = tid >> 5;
    const int wm = wid & 1;          // 0..1 : 64-row slab
    const int wn = wid >> 1;         // 0..3 : 32-col slab
    const int m0 = blockIdx.y * BM, n0 = blockIdx.x * BN;

    const float* A = Ag + (size_t)blockIdx.z * sA;
    const float* B = Bg + (size_t)blockIdx.z * sB;
    float*       C = Cg + (size_t)blockIdx.z * sC;
    const int nk = K / BK;

    // ---- loader mapping: 16B chunk c = tid + 256*i ; row=c>>3, kq=c&7 ----
    const int r0 = tid >> 3;                   // base row (0..31), +32*i
    const int kq = tid & 7;                    // 16B chunk within 128B row
    const uint32_t sxor = (uint32_t)((r0 & 7) << 4);
    uint32_t soff[4];
#pragma unroll
    for (int i = 0; i < 4; i++)
        soff[i] = (uint32_t)((r0 + 32 * i) * 128) + (((uint32_t)(kq * 16)) ^ sxor);

    const float* Arow = A + (size_t)(m0 + r0) * lda + kq * 4;
    const float* Brow = B + (size_t)(n0 + r0) * ldb + kq * 4;

    // ---- fragment-load mapping (ldmatrix) ----
    const int  rbase = lane & 15;
    const uint32_t xorv = (uint32_t)((lane & 7) << 4);
    const uint32_t kq16 = (uint32_t)((lane >> 4) << 4);   // 0 or 16 bytes

    float acc[4][4][4];
#pragma unroll
    for (int a = 0; a < 4; a++)
#pragma unroll
        for (int b = 0; b < 4; b++)
#pragma unroll
            for (int c = 0; c < 4; c++) acc[a][b][c] = 0.0f;

#define LOAD_STAGE(s, kc)                                                      \
    do {                                                                       \
        const uint32_t ab = sb + (s) * STAGE_B;                                \
        const float* ap = Arow + (size_t)(kc) * BK;                            \
        const float* bp = Brow + (size_t)(kc) * BK;                            \
        _Pragma("unroll")                                                      \
        for (int i = 0; i < 4; i++) {                                          \
            cpa16(ab + soff[i],          ap + (size_t)(32 * i) * lda);         \
            cpa16(ab + ATILE + soff[i],  bp + (size_t)(32 * i) * ldb);         \
        }                                                                      \
    } while (0)

    // prologue: stages 0,1
    LOAD_STAGE(0, 0);
    asm volatile("cp.async.commit_group;");
    LOAD_STAGE(1, 1);
    asm volatile("cp.async.commit_group;");

    for (int kc = 0; kc < nk; kc++) {
        asm volatile("cp.async.wait_group 1;");
        __syncthreads();

        if (kc + 2 < nk) {
            const int s = (kc + 2) % STAGES;
            LOAD_STAGE(s, kc + 2);
        }
        asm volatile("cp.async.commit_group;");

        // ---- compute on stage kc%STAGES ----
        const uint32_t stg = sb + (kc % STAGES) * STAGE_B;
        const uint32_t aB = stg + (uint32_t)((wm * 64 + rbase) * 128);
        const uint32_t bB = stg + ATILE + (uint32_t)((wn * 32 + rbase) * 128);
#pragma unroll
        for (int ks = 0; ks < 4; ks++) {
            const uint32_t kt = ((uint32_t)(ks * 32) + kq16) ^ xorv;
            uint32_t af[4][4], bf[2][4];
#pragma unroll
            for (int mt = 0; mt < 4; mt++) ldsm4(af[mt], aB + mt * 16 * 128 + kt);
#pragma unroll
            for (int bp = 0; bp < 2; bp++) ldsm4(bf[bp], bB + bp * 16 * 128 + kt);
#pragma unroll
            for (int mt = 0; mt < 4; mt++) {
                mma8(acc[mt][0], af[mt], bf[0][0], bf[0][2]);
                mma8(acc[mt][1], af[mt], bf[0][1], bf[0][3]);
                mma8(acc[mt][2], af[mt], bf[1][0], bf[1][2]);
                mma8(acc[mt][3], af[mt], bf[1][1], bf[1][3]);
            }
        }
        __syncthreads();
    }
#undef LOAD_STAGE

    // ---- epilogue ----
    const int g = lane >> 2, tg = lane & 3;
#pragma unroll
    for (int mt = 0; mt < 4; mt++) {
        const size_t rw0 = (size_t)(m0 + wm * 64 + mt * 16 + g) * ldc;
        const size_t rw1 = rw0 + (size_t)8 * ldc;
#pragma unroll
        for (int nt = 0; nt < 4; nt++) {
            const int col = n0 + wn * 32 + nt * 8 + tg * 2;
            float2 v0, v1;
            v0.x = acc[mt][nt][0] * alpha;
            v0.y = acc[mt][nt][1] * alpha;
            v1.x = acc[mt][nt][2] * alpha;
            v1.y = acc[mt][nt][3] * alpha;
            if (BIAS) {
                const float b0 = bias[col], b1 = bias[col + 1];
                v0.x += b0; v0.y += b1;
                v1.x += b0; v1.y += b1;
            }
            if (ROUND) {
                v0.x = tf32r(v0.x); v0.y = tf32r(v0.y);
                v1.x = tf32r(v1.x); v1.y = tf32r(v1.y);
            }
            *(float2*)(C + rw0 + col) = v0;
            *(float2*)(C + rw1 + col) = v1;
        }
    }
}

// ---------------------------------------------------------------------------
// round-to-tf32 copy (for x)
// ---------------------------------------------------------------------------
__global__ void round_copy4(const float4* __restrict__ in, float4* __restrict__ out, int n4)
{
    for (int i = blockIdx.x * blockDim.x + threadIdx.x; i < n4; i += gridDim.x * blockDim.x) {
        float4 v = in[i];
        v.x = tf32r(v.x); v.y = tf32r(v.y); v.z = tf32r(v.z); v.w = tf32r(v.w);
        out[i] = v;
    }
}

// ---------------------------------------------------------------------------
// Tiled transpose with tf32 rounding:  dst[c][r] = round(src[r][c])
// grid (C/32, R/32, batch), block (32,8)
// ---------------------------------------------------------------------------
__global__ void transpose_round_k(const float* __restrict__ src, float* __restrict__ dst,
                                  int ldS, int ldD, long long sS, long long sD)
{
    __shared__ float t[32][33];
    src += (size_t)blockIdx.z * sS;
    dst += (size_t)blockIdx.z * sD;
    const int c0 = blockIdx.x * 32, r0 = blockIdx.y * 32;
    const int tx = threadIdx.x, ty = threadIdx.y;
#pragma unroll
    for (int i = 0; i < 32; i += 8)
        t[ty + i][tx] = src[(size_t)(r0 + ty + i) * ldS + c0 + tx];
    __syncthreads();
#pragma unroll
    for (int i = 0; i < 32; i += 8)
        dst[(size_t)(c0 + ty + i) * ldD + r0 + tx] = tf32r(t[tx][ty + i]);
}

// ---------------------------------------------------------------------------
// Fused dual softmax with mask-fill (in place), tf32-rounded output.
// One CTA per (b,q) row of 2048; 256 threads, 8 values each.
// ---------------------------------------------------------------------------
__global__ __launch_bounds__(256)
void dual_softmax_k(float* __restrict__ scores, const int* __restrict__ mask)
{
    const long long row = blockIdx.x;
    float* s = scores + row * 2048;
    const int* mk = mask + row * 2048;
    const int tid = threadIdx.x;

    float v[8];
    int m[8];
#pragma unroll
    for (int i = 0; i < 8; ++i) {
        v[i] = s[tid + (i << 8)];
        m[i] = mk[tid + (i << 8)];
    }

    __shared__ float sred[8];

    // softmax 1: max
    float x = -3.0e38f;
#pragma unroll
    for (int i = 0; i < 8; ++i) x = fmaxf(x, v[i]);
#pragma unroll
    for (int o = 16; o > 0; o >>= 1) x = fmaxf(x, __shfl_xor_sync(0xffffffffu, x, o));
    if ((tid & 31) == 0) sred[tid >> 5] = x;
    __syncthreads();
    if (tid == 0) {
        float y = sred[0];
#pragma unroll
        for (int w = 1; w < 8; ++w) y = fmaxf(y, sred[w]);
        sred[0] = y;
    }
    __syncthreads();
    const float m1 = sred[0];
    __syncthreads();

    // softmax 1: exp + sum
    float su = 0.0f;
#pragma unroll
    for (int i = 0; i < 8; ++i) {
        v[i] = __expf(v[i] - m1);
        su += v[i];
    }
#pragma unroll
    for (int o = 16; o > 0; o >>= 1) su += __shfl_xor_sync(0xffffffffu, su, o);
    if ((tid & 31) == 0) sred[tid >> 5] = su;
    __syncthreads();
    if (tid == 0) {
        float y = 0.0f;
#pragma unroll
        for (int w = 0; w < 8; ++w) y += sred[w];
        sred[0] = y;
    }
    __syncthreads();
    const float inv1 = 1.0f / sred[0];
    __syncthreads();

#pragma unroll
    for (int i = 0; i < 8; ++i) v[i] *= inv1;

    // softmax 2: masked max
    float x2 = -1.0e30f;
#pragma unroll
    for (int i = 0; i < 8; ++i)
        if (m[i]) x2 = fmaxf(x2, v[i]);
#pragma unroll
    for (int o = 16; o > 0; o >>= 1) x2 = fmaxf(x2, __shfl_xor_sync(0xffffffffu, x2, o));
    if ((tid & 31) == 0) sred[tid >> 5] = x2;
    __syncthreads();
    if (tid == 0) {
        float y = sred[0];
#pragma unroll
        for (int w = 1; w < 8; ++w) y = fmaxf(y, sred[w]);
        sred[0] = y;
    }
    __syncthreads();
    const float m2 = sred[0];
    __syncthreads();

    if (m2 < -1.0e29f) {
        const float u = tf32r(1.0f / 2048.0f);
#pragma unroll
        for (int i = 0; i < 8; ++i) s[tid + (i << 8)] = u;
        return;
    }

    // softmax 2: masked exp + sum
    float su2 = 0.0f;
#pragma unroll
    for (int i = 0; i < 8; ++i) {
        const float e = m[i] ? __expf(v[i] - m2) : 0.0f;
        v[i] = e;
        su2 += e;
    }
#pragma unroll
    for (int o = 16; o > 0; o >>= 1) su2 += __shfl_xor_sync(0xffffffffu, su2, o);
    if ((tid & 31) == 0) sred[tid >> 5] = su2;
    __syncthreads();
    if (tid == 0) {
        float y = 0.0f;
#pragma unroll
        for (int w = 0; w < 8; ++w) y += sred[w];
        sred[0] = y;
    }
    __syncthreads();
    const float inv2 = 1.0f / sred[0];

#pragma unroll
    for (int i = 0; i < 8; ++i) s[tid + (i << 8)] = tf32r(v[i] * inv2);
}

// ---------------------------------------------------------------------------
// Launch
// ---------------------------------------------------------------------------
extern "C" void kernel_launch(void* const* d_in, const int* in_sizes, int n_in,
                              void* d_out, int out_size)
{
    (void)in_sizes; (void)n_in; (void)out_size;

    const float* x     = (const float*)d_in[0];
    const int*   mask  = (const int*)d_in[1];
    const float* W_qkv = (const float*)d_in[2];
    const float* b_qkv = (const float*)d_in[3];
    const float* W_out = (const float*)d_in[4];
    const float* b_out = (const float*)d_in[5];
    float* out = (float*)d_out;

    float *xr, *qkv, *scores, *att, *vT, *wqkvT, *woutT;
    cudaGetSymbolAddress((void**)&xr, g_xr);
    cudaGetSymbolAddress((void**)&qkv, g_qkv);
    cudaGetSymbolAddress((void**)&scores, g_scores);
    cudaGetSymbolAddress((void**)&att, g_att);
    cudaGetSymbolAddress((void**)&vT, g_vT);
    cudaGetSymbolAddress((void**)&wqkvT, g_wqkvT);
    cudaGetSymbolAddress((void**)&woutT, g_woutT);

    cudaFuncSetAttribute(gemm_tc<true,  true >, cudaFuncAttributeMaxDynamicSharedMemorySize, GEMM_SMEM);
    cudaFuncSetAttribute(gemm_tc<false, false>, cudaFuncAttributeMaxDynamicSharedMemorySize, GEMM_SMEM);
    cudaFuncSetAttribute(gemm_tc<false, true >, cudaFuncAttributeMaxDynamicSharedMemorySize, GEMM_SMEM);
    cudaFuncSetAttribute(gemm_tc<true,  false>, cudaFuncAttributeMaxDynamicSharedMemorySize, GEMM_SMEM);

    const int ROWS = BBATCH * SEQ;                     // 16384
    const long long sQKV = (long long)SEQ * 3 * DIM;
    const long long sSC  = (long long)SEQ * SEQ;
    const long long sAT  = (long long)SEQ * DIM;
    const long long sVT  = (long long)DIM * SEQ;

    // 0) round x to tf32
    round_copy4<<<4096, 256>>>((const float4*)x, (float4*)xr, ROWS * DIM / 4);

    // 0b) transpose + round weights
    transpose_round_k<<<dim3(3 * DIM / 32, DIM / 32, 1), dim3(32, 8)>>>(
        W_qkv, wqkvT, 3 * DIM, DIM, 0, 0);
    transpose_round_k<<<dim3(DIM / 32, DIM / 32, 1), dim3(32, 8)>>>(
        W_out, woutT, DIM, DIM, 0, 0);

    // 1) qkv = x @ W_qkv + b_qkv  (rounded)
    gemm_tc<true, true><<<dim3(3 * DIM / BN, ROWS / BM, 1), 256, GEMM_SMEM>>>(
        xr, wqkvT, qkv, b_qkv, DIM, DIM, 3 * DIM, 0, 0, 0, DIM, 1.0f);

    // 1b) V^T per batch
    transpose_round_k<<<dim3(DIM / 32, SEQ / 32, BBATCH), dim3(32, 8)>>>(
        qkv + 2 * DIM, vT, 3 * DIM, SEQ, sQKV, sVT);

    // 2) scores = Q @ K^T / 32
    gemm_tc<false, false><<<dim3(SEQ / BN, SEQ / BM, BBATCH), 256, GEMM_SMEM>>>(
        qkv, qkv + DIM, scores, nullptr, 3 * DIM, 3 * DIM, SEQ,
        sQKV, sQKV, sSC, DIM, 0.03125f);

    // 3) dual softmax + mask (in place, rounded)
    dual_softmax_k<<<ROWS, 256>>>(scores, mask);

    // 4) att = w @ V  (rounded)
    gemm_tc<false, true><<<dim3(DIM / BN, SEQ / BM, BBATCH), 256, GEMM_SMEM>>>(
        scores, vT, att, nullptr, SEQ, SEQ, DIM,
        sSC, sVT, sAT, SEQ, 1.0f);

    // 5) out = att @ W_out + b_out
    gemm_tc<true, false><<<dim3(DIM / BN, ROWS / BM, 1), 256, GEMM_SMEM>>>(
        att, woutT, out, b_out, DIM, DIM, DIM, 0, 0, 0, DIM, 1.0f);
}